// round 2
// baseline (speedup 1.0000x reference)
#include <cuda_runtime.h>

#define NN 50000
#define EE 400000
#define CC 128

__device__ float g_h [NN * CC];
__device__ float g_hn[NN * CC];
__device__ float g_x [NN * 3];
__device__ float g_xn[NN * 3];
__device__ float g_P [(size_t)NN * 1024];
__device__ float g_W3p[8 * 64 * 256];
__device__ float g_bp [8 * 256];

__device__ __forceinline__ float siluf(float v) { return v / (1.f + __expf(-v)); }

// fold We2/be2 into W1 rows [256:320)
__global__ void prep_kernel(const float* __restrict__ We2, const float* __restrict__ be2,
                            const float* __restrict__ Wn1, const float* __restrict__ bn1,
                            const float* __restrict__ Wc1, const float* __restrict__ bc1,
                            float* __restrict__ W3p, float* __restrict__ bp)
{
    int b = blockIdx.x, l = b >> 1, path = b & 1;
    const float* W1 = (path ? Wc1 : Wn1) + (size_t)l * 320 * 256;
    const float* bb = (path ? bc1 : bn1) + l * 256;
    const float* W2 = We2 + l * 64 * 64;
    const float* b2 = be2 + l * 64;
    int c = threadIdx.x;
    float acc[64];
#pragma unroll
    for (int k = 0; k < 64; k++) acc[k] = 0.f;
    float bacc = bb[c];
    for (int q = 0; q < 64; q++) {
        float w = W1[(size_t)(256 + q) * 256 + c];
        bacc += b2[q] * w;
#pragma unroll
        for (int k = 0; k < 64; k++) acc[k] += W2[k * 64 + q] * w;
    }
#pragma unroll
    for (int k = 0; k < 64; k++) W3p[(size_t)b * 16384 + k * 256 + c] = acc[k];
    bp[b * 256 + c] = bacc;
}

// P[N,1024] = h projections: by>>2 selects {Wn1 src, Wn1 dst, Wc1 src, Wc1 dst}
__global__ void __launch_bounds__(256) proj_kernel(const float* __restrict__ A,
                                                   const float* __restrict__ Wn1l,
                                                   const float* __restrict__ Wc1l,
                                                   float* __restrict__ P, int M)
{
    __shared__ float As[16][128];
    __shared__ float Bs[16][64];
    int bx = blockIdx.x, by = blockIdx.y;
    int q = by >> 2, colb = (by & 3) * 64;
    const float* W = (q < 2 ? Wn1l : Wc1l);
    int rowoff = (q & 1) * 128;
    int tid = threadIdx.x, tx = tid & 15, ty = tid >> 4;

    float acc[8][4];
#pragma unroll
    for (int i = 0; i < 8; i++)
#pragma unroll
        for (int j = 0; j < 4; j++) acc[i][j] = 0.f;

    for (int k0 = 0; k0 < 128; k0 += 16) {
#pragma unroll
        for (int s = 0; s < 2; s++) {
            int fid = tid * 2 + s;
            int r = fid >> 2, c4 = (fid & 3) << 2;
            int row = bx * 128 + r;
            float4 v = make_float4(0.f, 0.f, 0.f, 0.f);
            if (row < M) v = *(const float4*)(A + (size_t)row * 128 + k0 + c4);
            As[c4 + 0][r] = v.x; As[c4 + 1][r] = v.y; As[c4 + 2][r] = v.z; As[c4 + 3][r] = v.w;
        }
        {
            int r = tid >> 4, c4 = (tid & 15) << 2;
            *(float4*)(&Bs[r][c4]) = *(const float4*)(W + (size_t)(rowoff + k0 + r) * 256 + colb + c4);
        }
        __syncthreads();
#pragma unroll
        for (int k = 0; k < 16; k++) {
            float a[8];
#pragma unroll
            for (int i = 0; i < 8; i++) a[i] = As[k][ty * 8 + i];
            float4 b = *(const float4*)(&Bs[k][tx * 4]);
#pragma unroll
            for (int i = 0; i < 8; i++) {
                acc[i][0] += a[i] * b.x; acc[i][1] += a[i] * b.y;
                acc[i][2] += a[i] * b.z; acc[i][3] += a[i] * b.w;
            }
        }
        __syncthreads();
    }
#pragma unroll
    for (int i = 0; i < 8; i++) {
        int row = bx * 128 + ty * 8 + i;
        if (row < M)
            *(float4*)(P + (size_t)row * 1024 + by * 64 + tx * 4) =
                make_float4(acc[i][0], acc[i][1], acc[i][2], acc[i][3]);
    }
}

#define SM_EA   0
#define SM_S    (64 * 68)
#define SM_WS   (SM_S + 64 * 260)
#define SM_CW   (SM_WS + 4096)
#define SM_IDX  (SM_CW + 256)
#define SMEM_EDGE_BYTES ((SM_IDX + 128) * 4)

__device__ __forceinline__ void phaseA(const float* __restrict__ W3p, const float* __restrict__ bp,
                                       const float* __restrict__ P, int poff,
                                       const int* __restrict__ sIdx, const int* __restrict__ dIdx,
                                       const float* __restrict__ Ea, float* __restrict__ S,
                                       float* __restrict__ Ws, int ty, int tx)
{
    float acc[4][16];
#pragma unroll
    for (int i = 0; i < 4; i++) {
        int m = ty * 4 + i;
        const float* Ps = P + (size_t)sIdx[m] * 1024 + poff;
        const float* Pd = P + (size_t)dIdx[m] * 1024 + poff + 256;
#pragma unroll
        for (int jh = 0; jh < 4; jh++) {
            int c = jh * 64 + tx * 4;
            float4 bb = *(const float4*)(bp + c);
            float4 ps = *(const float4*)(Ps + c);
            float4 pd = *(const float4*)(Pd + c);
            acc[i][jh * 4 + 0] = bb.x + ps.x + pd.x;
            acc[i][jh * 4 + 1] = bb.y + ps.y + pd.y;
            acc[i][jh * 4 + 2] = bb.z + ps.z + pd.z;
            acc[i][jh * 4 + 3] = bb.w + ps.w + pd.w;
        }
    }
    int tid = ty * 16 + tx;
    for (int kc = 0; kc < 4; kc++) {
#pragma unroll
        for (int s = 0; s < 4; s++) {
            int fid = tid + s * 256;
            int r = fid >> 6, c4 = (fid & 63) << 2;
            *(float4*)(Ws + r * 256 + c4) = *(const float4*)(W3p + (size_t)(kc * 16 + r) * 256 + c4);
        }
        __syncthreads();
#pragma unroll
        for (int k = 0; k < 16; k++) {
            float a0 = Ea[(ty * 4 + 0) * 68 + kc * 16 + k];
            float a1 = Ea[(ty * 4 + 1) * 68 + kc * 16 + k];
            float a2 = Ea[(ty * 4 + 2) * 68 + kc * 16 + k];
            float a3 = Ea[(ty * 4 + 3) * 68 + kc * 16 + k];
#pragma unroll
            for (int jh = 0; jh < 4; jh++) {
                float4 b = *(const float4*)(Ws + k * 256 + jh * 64 + tx * 4);
                acc[0][jh * 4 + 0] += a0 * b.x; acc[0][jh * 4 + 1] += a0 * b.y;
                acc[0][jh * 4 + 2] += a0 * b.z; acc[0][jh * 4 + 3] += a0 * b.w;
                acc[1][jh * 4 + 0] += a1 * b.x; acc[1][jh * 4 + 1] += a1 * b.y;
                acc[1][jh * 4 + 2] += a1 * b.z; acc[1][jh * 4 + 3] += a1 * b.w;
                acc[2][jh * 4 + 0] += a2 * b.x; acc[2][jh * 4 + 1] += a2 * b.y;
                acc[2][jh * 4 + 2] += a2 * b.z; acc[2][jh * 4 + 3] += a2 * b.w;
                acc[3][jh * 4 + 0] += a3 * b.x; acc[3][jh * 4 + 1] += a3 * b.y;
                acc[3][jh * 4 + 2] += a3 * b.z; acc[3][jh * 4 + 3] += a3 * b.w;
            }
        }
        __syncthreads();
    }
#pragma unroll
    for (int i = 0; i < 4; i++) {
        int m = ty * 4 + i;
#pragma unroll
        for (int jh = 0; jh < 4; jh++)
#pragma unroll
            for (int jl = 0; jl < 4; jl++)
                S[m * 260 + jh * 64 + tx * 4 + jl] = siluf(acc[i][jh * 4 + jl]);
    }
}

__global__ void __launch_bounds__(256, 2) edge_kernel(
    const int* __restrict__ srcIdx, const int* __restrict__ dstIdx,
    const float* __restrict__ dist,
    const float* __restrict__ We1l, const float* __restrict__ be1l,
    const float* __restrict__ W3pn, const float* __restrict__ bpn,
    const float* __restrict__ W3pc, const float* __restrict__ bpc,
    const float* __restrict__ Wn2l, const float* __restrict__ bn2l,
    const float* __restrict__ Wc2l,
    const float* __restrict__ P, const float* __restrict__ x,
    float* __restrict__ hn, float* __restrict__ xn)
{
    extern __shared__ float sm[];
    float* Ea = sm + SM_EA;
    float* S  = sm + SM_S;
    float* Ws = sm + SM_WS;
    float* cwPart = sm + SM_CW;
    int* sIdx = (int*)(sm + SM_IDX);
    int* dIdx = sIdx + 64;

    int tid = threadIdx.x;
    int tx = tid & 15, ty = tid >> 4;
    int e0 = blockIdx.x * 64;

    if (tid < 64) { sIdx[tid] = srcIdx[e0 + tid]; dIdx[tid] = dstIdx[e0 + tid]; }
    {
        int m = tid >> 2, seg = tid & 3;
        float d = dist[e0 + m];
#pragma unroll
        for (int kk = 0; kk < 16; kk++) {
            int k = seg * 16 + kk;
            Ea[m * 68 + k] = siluf(d * We1l[k] + be1l[k]);
        }
    }
    __syncthreads();

    phaseA(W3pn, bpn, P, 0, sIdx, dIdx, Ea, S, Ws, ty, tx);
    __syncthreads();

    {   // m = S @ Wn2 + bn2 ; scatter
        float acc2[4][8];
#pragma unroll
        for (int i = 0; i < 4; i++)
#pragma unroll
            for (int jh = 0; jh < 2; jh++) {
                float4 bb = *(const float4*)(bn2l + jh * 64 + tx * 4);
                acc2[i][jh * 4 + 0] = bb.x; acc2[i][jh * 4 + 1] = bb.y;
                acc2[i][jh * 4 + 2] = bb.z; acc2[i][jh * 4 + 3] = bb.w;
            }
        for (int kc = 0; kc < 8; kc++) {
#pragma unroll
            for (int s = 0; s < 4; s++) {
                int fid = tid + s * 256;
                int r = fid >> 5, c4 = (fid & 31) << 2;
                *(float4*)(Ws + r * 128 + c4) = *(const float4*)(Wn2l + (size_t)(kc * 32 + r) * 128 + c4);
            }
            __syncthreads();
#pragma unroll
            for (int k = 0; k < 32; k++) {
                float a0 = S[(ty * 4 + 0) * 260 + kc * 32 + k];
                float a1 = S[(ty * 4 + 1) * 260 + kc * 32 + k];
                float a2 = S[(ty * 4 + 2) * 260 + kc * 32 + k];
                float a3 = S[(ty * 4 + 3) * 260 + kc * 32 + k];
#pragma unroll
                for (int jh = 0; jh < 2; jh++) {
                    float4 b = *(const float4*)(Ws + k * 128 + jh * 64 + tx * 4);
                    acc2[0][jh * 4 + 0] += a0 * b.x; acc2[0][jh * 4 + 1] += a0 * b.y;
                    acc2[0][jh * 4 + 2] += a0 * b.z; acc2[0][jh * 4 + 3] += a0 * b.w;
                    acc2[1][jh * 4 + 0] += a1 * b.x; acc2[1][jh * 4 + 1] += a1 * b.y;
                    acc2[1][jh * 4 + 2] += a1 * b.z; acc2[1][jh * 4 + 3] += a1 * b.w;
                    acc2[2][jh * 4 + 0] += a2 * b.x; acc2[2][jh * 4 + 1] += a2 * b.y;
                    acc2[2][jh * 4 + 2] += a2 * b.z; acc2[2][jh * 4 + 3] += a2 * b.w;
                    acc2[3][jh * 4 + 0] += a3 * b.x; acc2[3][jh * 4 + 1] += a3 * b.y;
                    acc2[3][jh * 4 + 2] += a3 * b.z; acc2[3][jh * 4 + 3] += a3 * b.w;
                }
            }
            __syncthreads();
        }
#pragma unroll
        for (int i = 0; i < 4; i++) {
            float* base = hn + (size_t)dIdx[ty * 4 + i] * 128;
#pragma unroll
            for (int jh = 0; jh < 2; jh++)
#pragma unroll
                for (int jl = 0; jl < 4; jl++)
                    atomicAdd(base + jh * 64 + tx * 4 + jl, acc2[i][jh * 4 + jl]);
        }
    }

    phaseA(W3pc, bpc, P, 512, sIdx, dIdx, Ea, S, Ws, ty, tx);
    __syncthreads();

    {   // cw = S @ Wc2 ; coord scatter
        int m = tid >> 2, part = tid & 3;
        const float* wc = Wc2l + part * 64;
        const float* Sr = S + m * 260 + part * 64;
        float sum = 0.f;
#pragma unroll
        for (int k = 0; k < 64; k++) sum += Sr[k] * wc[k];
        cwPart[m * 4 + part] = sum;
        __syncthreads();
        if (tid < 64) {
            float cw = cwPart[tid * 4] + cwPart[tid * 4 + 1] + cwPart[tid * 4 + 2] + cwPart[tid * 4 + 3];
            int s = sIdx[tid], dd = dIdx[tid];
            atomicAdd(xn + (size_t)dd * 3 + 0, cw * (x[(size_t)s * 3 + 0] - x[(size_t)dd * 3 + 0]));
            atomicAdd(xn + (size_t)dd * 3 + 1, cw * (x[(size_t)s * 3 + 1] - x[(size_t)dd * 3 + 1]));
            atomicAdd(xn + (size_t)dd * 3 + 2, cw * (x[(size_t)s * 3 + 2] - x[(size_t)dd * 3 + 2]));
        }
    }
}

__global__ void ln_kernel(const float* __restrict__ h, const float* __restrict__ x,
                          const float* __restrict__ gamma, const float* __restrict__ beta,
                          float* __restrict__ out)
{
    int g = blockIdx.x * blockDim.x + threadIdx.x;
    int w = g >> 5, lane = g & 31;
    if (w < NN) {
        const float* row = h + (size_t)w * CC;
        float v0 = row[lane], v1 = row[lane + 32], v2 = row[lane + 64], v3 = row[lane + 96];
        float s = v0 + v1 + v2 + v3;
#pragma unroll
        for (int o = 16; o > 0; o >>= 1) s += __shfl_xor_sync(0xffffffffu, s, o);
        float mu = s * (1.f / 128.f);
        float d0 = v0 - mu, d1 = v1 - mu, d2 = v2 - mu, d3 = v3 - mu;
        float q = d0 * d0 + d1 * d1 + d2 * d2 + d3 * d3;
#pragma unroll
        for (int o = 16; o > 0; o >>= 1) q += __shfl_xor_sync(0xffffffffu, q, o);
        float rs = rsqrtf(q * (1.f / 128.f) + 1e-5f);
        float* orow = out + (size_t)w * CC;
        orow[lane]      = gamma[lane]      * d0 * rs + beta[lane];
        orow[lane + 32] = gamma[lane + 32] * d1 * rs + beta[lane + 32];
        orow[lane + 64] = gamma[lane + 64] * d2 * rs + beta[lane + 64];
        orow[lane + 96] = gamma[lane + 96] * d3 * rs + beta[lane + 96];
    }
    int stride = gridDim.x * blockDim.x;
    for (int j = g; j < NN * 3; j += stride) out[(size_t)NN * CC + j] = x[j];
}

extern "C" void kernel_launch(void* const* d_in, const int* in_sizes, int n_in,
                              void* d_out, int out_size)
{
    (void)in_sizes; (void)n_in; (void)out_size;
    const float* single = (const float*)d_in[0];
    const float* coords = (const float*)d_in[2];
    const int*   eidx   = (const int*)d_in[3];
    const float* dist   = (const float*)d_in[4];
    const float* We1 = (const float*)d_in[5];
    const float* be1 = (const float*)d_in[6];
    const float* We2 = (const float*)d_in[7];
    const float* be2 = (const float*)d_in[8];
    const float* Wn1 = (const float*)d_in[9];
    const float* bn1 = (const float*)d_in[10];
    const float* Wn2 = (const float*)d_in[11];
    const float* bn2 = (const float*)d_in[12];
    const float* Wc1 = (const float*)d_in[13];
    const float* bc1 = (const float*)d_in[14];
    const float* Wc2 = (const float*)d_in[15];
    const float* gamma = (const float*)d_in[16];
    const float* beta  = (const float*)d_in[17];
    float* out = (float*)d_out;

    float *h, *hn, *x, *xn, *P, *W3p, *bp;
    cudaGetSymbolAddress((void**)&h,   g_h);
    cudaGetSymbolAddress((void**)&hn,  g_hn);
    cudaGetSymbolAddress((void**)&x,   g_x);
    cudaGetSymbolAddress((void**)&xn,  g_xn);
    cudaGetSymbolAddress((void**)&P,   g_P);
    cudaGetSymbolAddress((void**)&W3p, g_W3p);
    cudaGetSymbolAddress((void**)&bp,  g_bp);

    cudaFuncSetAttribute(edge_kernel, cudaFuncAttributeMaxDynamicSharedMemorySize, SMEM_EDGE_BYTES);

    prep_kernel<<<8, 256>>>(We2, be2, Wn1, bn1, Wc1, bc1, W3p, bp);
    cudaMemcpyAsync(h, single, sizeof(float) * NN * CC, cudaMemcpyDeviceToDevice, 0);
    cudaMemcpyAsync(x, coords, sizeof(float) * NN * 3, cudaMemcpyDeviceToDevice, 0);

    const int* srcI = eidx;
    const int* dstI = eidx + EE;

    for (int l = 0; l < 4; l++) {
        cudaMemcpyAsync(hn, h, sizeof(float) * NN * CC, cudaMemcpyDeviceToDevice, 0);
        cudaMemcpyAsync(xn, x, sizeof(float) * NN * 3, cudaMemcpyDeviceToDevice, 0);
        dim3 gp((NN + 127) / 128, 16);
        proj_kernel<<<gp, 256>>>(h, Wn1 + (size_t)l * 320 * 256, Wc1 + (size_t)l * 320 * 256, P, NN);
        edge_kernel<<<EE / 64, 256, SMEM_EDGE_BYTES>>>(
            srcI, dstI, dist,
            We1 + l * 64, be1 + l * 64,
            W3p + (size_t)(2 * l) * 16384, bp + (2 * l) * 256,
            W3p + (size_t)(2 * l + 1) * 16384, bp + (2 * l + 1) * 256,
            Wn2 + (size_t)l * 256 * 128, bn2 + l * 128,
            Wc2 + (size_t)l * 256,
            P, x, hn, xn);
        float* t;
        t = h; h = hn; hn = t;
        t = x; x = xn; xn = t;
    }
    ln_kernel<<<(NN * 32 + 255) / 256, 256>>>(h, x, gamma, beta, out);
}

// round 3
// speedup vs baseline: 1.4540x; 1.4540x over previous
#include <cuda_runtime.h>

#define NN 50000
#define EE 400000
#define CC 128

__device__ float g_h   [NN * CC];
__device__ float g_hn  [NN * CC];
__device__ float g_x   [NN * 3];
__device__ float g_xn  [NN * 3];
__device__ float g_P   [(size_t)NN * 1024];
__device__ float g_Wsw [8 * 64 * 256];   // swizzled tf32 folded weights, per (layer,path)
__device__ float g_bp  [8 * 256];
__device__ float g_aggS[(size_t)NN * 256];
__device__ float g_deg [NN];

__device__ __forceinline__ float siluf(float v) { return v / (1.f + __expf(-v)); }

__device__ __forceinline__ unsigned tf32r(float v) {
    unsigned u;
    asm("cvt.rna.tf32.f32 %0, %1;" : "=r"(u) : "f"(v));
    return u;
}

__device__ __forceinline__ void mma8(float* C, unsigned a0, unsigned a1, unsigned a2, unsigned a3,
                                     unsigned b0, unsigned b1) {
    asm volatile("mma.sync.aligned.m16n8k8.row.col.f32.tf32.tf32.f32 "
                 "{%0,%1,%2,%3}, {%4,%5,%6,%7}, {%8,%9}, {%0,%1,%2,%3};"
                 : "+f"(C[0]), "+f"(C[1]), "+f"(C[2]), "+f"(C[3])
                 : "r"(a0), "r"(a1), "r"(a2), "r"(a3), "r"(b0), "r"(b1));
}

// fold We2/be2 into W1 rows [256:320); emit tf32-rounded, B-fragment-swizzled layout.
// swizzle: idx(k,n) = ((k>>3)*32 + (n>>3))*64 + (n&7)*8 + (k&3)*2 + ((k&7)>>2)
__global__ void prep_kernel(const float* __restrict__ We2, const float* __restrict__ be2,
                            const float* __restrict__ Wn1, const float* __restrict__ bn1,
                            const float* __restrict__ Wc1, const float* __restrict__ bc1,
                            float* __restrict__ Wsw, float* __restrict__ bp)
{
    int b = blockIdx.x, l = b >> 1, path = b & 1;
    const float* W1 = (path ? Wc1 : Wn1) + (size_t)l * 320 * 256;
    const float* bb = (path ? bc1 : bn1) + l * 256;
    const float* W2 = We2 + l * 64 * 64;
    const float* b2 = be2 + l * 64;
    int c = threadIdx.x;   // output column n
    float acc[64];
#pragma unroll
    for (int k = 0; k < 64; k++) acc[k] = 0.f;
    float bacc = bb[c];
    for (int q = 0; q < 64; q++) {
        float w = W1[(size_t)(256 + q) * 256 + c];
        bacc += b2[q] * w;
#pragma unroll
        for (int k = 0; k < 64; k++) acc[k] += W2[k * 64 + q] * w;
    }
#pragma unroll
    for (int k = 0; k < 64; k++) {
        int idx = ((k >> 3) * 32 + (c >> 3)) * 64 + (c & 7) * 8 + (k & 3) * 2 + ((k & 7) >> 2);
        Wsw[(size_t)b * 16384 + idx] = __uint_as_float(tf32r(acc[k]));
    }
    bp[b * 256 + c] = bacc;
}

__global__ void deg_kernel(const int* __restrict__ dstIdx, float* __restrict__ deg) {
    int e = blockIdx.x * blockDim.x + threadIdx.x;
    if (e < EE) atomicAdd(&deg[dstIdx[e]], 1.0f);
}

// P[N,1024] = h projections: by>>2 selects {Wn1 src, Wn1 dst, Wc1 src, Wc1 dst}
__global__ void __launch_bounds__(256) proj_kernel(const float* __restrict__ A,
                                                   const float* __restrict__ Wn1l,
                                                   const float* __restrict__ Wc1l,
                                                   float* __restrict__ P, int M)
{
    __shared__ float As[16][128];
    __shared__ float Bs[16][64];
    int bx = blockIdx.x, by = blockIdx.y;
    int q = by >> 2, colb = (by & 3) * 64;
    const float* W = (q < 2 ? Wn1l : Wc1l);
    int rowoff = (q & 1) * 128;
    int tid = threadIdx.x, tx = tid & 15, ty = tid >> 4;

    float acc[8][4];
#pragma unroll
    for (int i = 0; i < 8; i++)
#pragma unroll
        for (int j = 0; j < 4; j++) acc[i][j] = 0.f;

    for (int k0 = 0; k0 < 128; k0 += 16) {
#pragma unroll
        for (int s = 0; s < 2; s++) {
            int fid = tid * 2 + s;
            int r = fid >> 2, c4 = (fid & 3) << 2;
            int row = bx * 128 + r;
            float4 v = make_float4(0.f, 0.f, 0.f, 0.f);
            if (row < M) v = *(const float4*)(A + (size_t)row * 128 + k0 + c4);
            As[c4 + 0][r] = v.x; As[c4 + 1][r] = v.y; As[c4 + 2][r] = v.z; As[c4 + 3][r] = v.w;
        }
        {
            int r = tid >> 4, c4 = (tid & 15) << 2;
            *(float4*)(&Bs[r][c4]) = *(const float4*)(W + (size_t)(rowoff + k0 + r) * 256 + colb + c4);
        }
        __syncthreads();
#pragma unroll
        for (int k = 0; k < 16; k++) {
            float a[8];
#pragma unroll
            for (int i = 0; i < 8; i++) a[i] = As[k][ty * 8 + i];
            float4 b = *(const float4*)(&Bs[k][tx * 4]);
#pragma unroll
            for (int i = 0; i < 8; i++) {
                acc[i][0] += a[i] * b.x; acc[i][1] += a[i] * b.y;
                acc[i][2] += a[i] * b.z; acc[i][3] += a[i] * b.w;
            }
        }
        __syncthreads();
    }
#pragma unroll
    for (int i = 0; i < 8; i++) {
        int row = bx * 128 + ty * 8 + i;
        if (row < M)
            *(float4*)(P + (size_t)row * 1024 + by * 64 + tx * 4) =
                make_float4(acc[i][0], acc[i][1], acc[i][2], acc[i][3]);
    }
}

// fused edge kernel: tf32 mma for edge term, fragment-resident epilogue,
// S aggregated per dst into aggS (atomics), coord path scatters into xn.
__global__ void __launch_bounds__(256, 2) edge_kernel(
    const int* __restrict__ srcIdx, const int* __restrict__ dstIdx,
    const float* __restrict__ dist,
    const float* __restrict__ We1l, const float* __restrict__ be1l,
    const float* __restrict__ Wswn, const float* __restrict__ bpn,
    const float* __restrict__ Wswc, const float* __restrict__ bpc,
    const float* __restrict__ Wc2l,
    const float* __restrict__ P, const float* __restrict__ x,
    float* __restrict__ aggS, float* __restrict__ xn)
{
    __shared__ float Ea[64 * 68];
    __shared__ float bpS[512];
    __shared__ float Wc2s[256];
    __shared__ float cwP[128];
    __shared__ int sIdx[64], dIdx[64];

    int tid = threadIdx.x;
    int lane = tid & 31, w = tid >> 5;
    int gid = lane >> 2, tig = lane & 3;
    int m0 = (w & 3) * 16;
    int jb = (w >> 2) * 16;           // n0 = jb*8
    int e0 = blockIdx.x * 64;

    if (tid < 64) { sIdx[tid] = srcIdx[e0 + tid]; dIdx[tid] = dstIdx[e0 + tid]; }
    bpS[tid] = bpn[tid];
    bpS[256 + tid] = bpc[tid];
    Wc2s[tid] = Wc2l[tid];
    {
        int m = tid >> 2, seg = tid & 3;
        float d = dist[e0 + m];
#pragma unroll
        for (int kk = 0; kk < 16; kk++) {
            int k = seg * 16 + kk;
            Ea[m * 68 + k] = __uint_as_float(tf32r(siluf(fmaf(d, We1l[k], be1l[k]))));
        }
    }
    __syncthreads();

    int r0 = m0 + gid, r1 = r0 + 8;
    int s0 = sIdx[r0], d0i = dIdx[r0];
    int s1 = sIdx[r1], d1i = dIdx[r1];

    float Cacc[64];

    // ================= path n (message) =================
#pragma unroll
    for (int i = 0; i < 64; i++) Cacc[i] = 0.f;
    for (int kk = 0; kk < 8; kk++) {
        unsigned a0 = __float_as_uint(Ea[r0 * 68 + kk * 8 + tig]);
        unsigned a1 = __float_as_uint(Ea[r1 * 68 + kk * 8 + tig]);
        unsigned a2 = __float_as_uint(Ea[r0 * 68 + kk * 8 + tig + 4]);
        unsigned a3 = __float_as_uint(Ea[r1 * 68 + kk * 8 + tig + 4]);
#pragma unroll
        for (int j = 0; j < 16; j++) {
            float2 bb = *(const float2*)(Wswn + (size_t)(kk * 32 + jb + j) * 64 + lane * 2);
            mma8(Cacc + j * 4, a0, a1, a2, a3, __float_as_uint(bb.x), __float_as_uint(bb.y));
        }
    }
#pragma unroll
    for (int j = 0; j < 16; j++) {
        int cc = (jb + j) * 8 + tig * 2;
        float2 bb = *(const float2*)(bpS + cc);
        float2 ps = *(const float2*)(P + (size_t)s0 * 1024 + cc);
        float2 pd = *(const float2*)(P + (size_t)d0i * 1024 + 256 + cc);
        float v0 = siluf(Cacc[j * 4 + 0] + bb.x + ps.x + pd.x);
        float v1 = siluf(Cacc[j * 4 + 1] + bb.y + ps.y + pd.y);
        atomicAdd(aggS + (size_t)d0i * 256 + cc, v0);
        atomicAdd(aggS + (size_t)d0i * 256 + cc + 1, v1);
        ps = *(const float2*)(P + (size_t)s1 * 1024 + cc);
        pd = *(const float2*)(P + (size_t)d1i * 1024 + 256 + cc);
        v0 = siluf(Cacc[j * 4 + 2] + bb.x + ps.x + pd.x);
        v1 = siluf(Cacc[j * 4 + 3] + bb.y + ps.y + pd.y);
        atomicAdd(aggS + (size_t)d1i * 256 + cc, v0);
        atomicAdd(aggS + (size_t)d1i * 256 + cc + 1, v1);
    }

    // ================= path c (coordinates) =================
#pragma unroll
    for (int i = 0; i < 64; i++) Cacc[i] = 0.f;
    for (int kk = 0; kk < 8; kk++) {
        unsigned a0 = __float_as_uint(Ea[r0 * 68 + kk * 8 + tig]);
        unsigned a1 = __float_as_uint(Ea[r1 * 68 + kk * 8 + tig]);
        unsigned a2 = __float_as_uint(Ea[r0 * 68 + kk * 8 + tig + 4]);
        unsigned a3 = __float_as_uint(Ea[r1 * 68 + kk * 8 + tig + 4]);
#pragma unroll
        for (int j = 0; j < 16; j++) {
            float2 bb = *(const float2*)(Wswc + (size_t)(kk * 32 + jb + j) * 64 + lane * 2);
            mma8(Cacc + j * 4, a0, a1, a2, a3, __float_as_uint(bb.x), __float_as_uint(bb.y));
        }
    }
    float p0 = 0.f, p1 = 0.f;
#pragma unroll
    for (int j = 0; j < 16; j++) {
        int cc = (jb + j) * 8 + tig * 2;
        float2 bb = *(const float2*)(bpS + 256 + cc);
        float2 wc = *(const float2*)(Wc2s + cc);
        float2 ps = *(const float2*)(P + (size_t)s0 * 1024 + 512 + cc);
        float2 pd = *(const float2*)(P + (size_t)d0i * 1024 + 768 + cc);
        p0 += siluf(Cacc[j * 4 + 0] + bb.x + ps.x + pd.x) * wc.x
            + siluf(Cacc[j * 4 + 1] + bb.y + ps.y + pd.y) * wc.y;
        ps = *(const float2*)(P + (size_t)s1 * 1024 + 512 + cc);
        pd = *(const float2*)(P + (size_t)d1i * 1024 + 768 + cc);
        p1 += siluf(Cacc[j * 4 + 2] + bb.x + ps.x + pd.x) * wc.x
            + siluf(Cacc[j * 4 + 3] + bb.y + ps.y + pd.y) * wc.y;
    }
    p0 += __shfl_xor_sync(0xffffffffu, p0, 1);
    p0 += __shfl_xor_sync(0xffffffffu, p0, 2);
    p1 += __shfl_xor_sync(0xffffffffu, p1, 1);
    p1 += __shfl_xor_sync(0xffffffffu, p1, 2);
    if (tig == 0) {
        cwP[r0 * 2 + (w >> 2)] = p0;
        cwP[r1 * 2 + (w >> 2)] = p1;
    }
    __syncthreads();
    if (tid < 64) {
        float cw = cwP[tid * 2] + cwP[tid * 2 + 1];
        int s = sIdx[tid], dd = dIdx[tid];
        atomicAdd(&xn[(size_t)dd * 3 + 0], cw * (x[(size_t)s * 3 + 0] - x[(size_t)dd * 3 + 0]));
        atomicAdd(&xn[(size_t)dd * 3 + 1], cw * (x[(size_t)s * 3 + 1] - x[(size_t)dd * 3 + 1]));
        atomicAdd(&xn[(size_t)dd * 3 + 2], cw * (x[(size_t)s * 3 + 2] - x[(size_t)dd * 3 + 2]));
    }
}

// hn = h + aggS @ Wn2 + deg * bn2
__global__ void __launch_bounds__(256) nupd_kernel(const float* __restrict__ A,
                                                   const float* __restrict__ W,
                                                   const float* __restrict__ bn2l,
                                                   const float* __restrict__ hprev,
                                                   const float* __restrict__ deg,
                                                   float* __restrict__ hn, int M)
{
    __shared__ float As[16][128];
    __shared__ float Bs[16][64];
    int bx = blockIdx.x, by = blockIdx.y;
    int colb = by * 64;
    int tid = threadIdx.x, tx = tid & 15, ty = tid >> 4;

    float acc[8][4];
#pragma unroll
    for (int i = 0; i < 8; i++)
#pragma unroll
        for (int j = 0; j < 4; j++) acc[i][j] = 0.f;

    for (int k0 = 0; k0 < 256; k0 += 16) {
#pragma unroll
        for (int s = 0; s < 2; s++) {
            int fid = tid * 2 + s;
            int r = fid >> 2, c4 = (fid & 3) << 2;
            int row = bx * 128 + r;
            float4 v = make_float4(0.f, 0.f, 0.f, 0.f);
            if (row < M) v = *(const float4*)(A + (size_t)row * 256 + k0 + c4);
            As[c4 + 0][r] = v.x; As[c4 + 1][r] = v.y; As[c4 + 2][r] = v.z; As[c4 + 3][r] = v.w;
        }
        {
            int r = tid >> 4, c4 = (tid & 15) << 2;
            *(float4*)(&Bs[r][c4]) = *(const float4*)(W + (size_t)(k0 + r) * 128 + colb + c4);
        }
        __syncthreads();
#pragma unroll
        for (int k = 0; k < 16; k++) {
            float a[8];
#pragma unroll
            for (int i = 0; i < 8; i++) a[i] = As[k][ty * 8 + i];
            float4 b = *(const float4*)(&Bs[k][tx * 4]);
#pragma unroll
            for (int i = 0; i < 8; i++) {
                acc[i][0] += a[i] * b.x; acc[i][1] += a[i] * b.y;
                acc[i][2] += a[i] * b.z; acc[i][3] += a[i] * b.w;
            }
        }
        __syncthreads();
    }
#pragma unroll
    for (int i = 0; i < 8; i++) {
        int row = bx * 128 + ty * 8 + i;
        if (row < M) {
            int col = colb + tx * 4;
            float dg = deg[row];
            float4 hh = *(const float4*)(hprev + (size_t)row * 128 + col);
            float4 bb = *(const float4*)(bn2l + col);
            float4 o;
            o.x = acc[i][0] + hh.x + dg * bb.x;
            o.y = acc[i][1] + hh.y + dg * bb.y;
            o.z = acc[i][2] + hh.z + dg * bb.z;
            o.w = acc[i][3] + hh.w + dg * bb.w;
            *(float4*)(hn + (size_t)row * 128 + col) = o;
        }
    }
}

__global__ void ln_kernel(const float* __restrict__ h, const float* __restrict__ x,
                          const float* __restrict__ gamma, const float* __restrict__ beta,
                          float* __restrict__ out)
{
    int g = blockIdx.x * blockDim.x + threadIdx.x;
    int w = g >> 5, lane = g & 31;
    if (w < NN) {
        const float* row = h + (size_t)w * CC;
        float v0 = row[lane], v1 = row[lane + 32], v2 = row[lane + 64], v3 = row[lane + 96];
        float s = v0 + v1 + v2 + v3;
#pragma unroll
        for (int o = 16; o > 0; o >>= 1) s += __shfl_xor_sync(0xffffffffu, s, o);
        float mu = s * (1.f / 128.f);
        float d0 = v0 - mu, d1 = v1 - mu, d2 = v2 - mu, d3 = v3 - mu;
        float q = d0 * d0 + d1 * d1 + d2 * d2 + d3 * d3;
#pragma unroll
        for (int o = 16; o > 0; o >>= 1) q += __shfl_xor_sync(0xffffffffu, q, o);
        float rs = rsqrtf(q * (1.f / 128.f) + 1e-5f);
        float* orow = out + (size_t)w * CC;
        orow[lane]      = gamma[lane]      * d0 * rs + beta[lane];
        orow[lane + 32] = gamma[lane + 32] * d1 * rs + beta[lane + 32];
        orow[lane + 64] = gamma[lane + 64] * d2 * rs + beta[lane + 64];
        orow[lane + 96] = gamma[lane + 96] * d3 * rs + beta[lane + 96];
    }
    int stride = gridDim.x * blockDim.x;
    for (int j = g; j < NN * 3; j += stride) out[(size_t)NN * CC + j] = x[j];
}

extern "C" void kernel_launch(void* const* d_in, const int* in_sizes, int n_in,
                              void* d_out, int out_size)
{
    (void)in_sizes; (void)n_in; (void)out_size;
    const float* single = (const float*)d_in[0];
    const float* coords = (const float*)d_in[2];
    const int*   eidx   = (const int*)d_in[3];
    const float* dist   = (const float*)d_in[4];
    const float* We1 = (const float*)d_in[5];
    const float* be1 = (const float*)d_in[6];
    const float* We2 = (const float*)d_in[7];
    const float* be2 = (const float*)d_in[8];
    const float* Wn1 = (const float*)d_in[9];
    const float* bn1 = (const float*)d_in[10];
    const float* Wn2 = (const float*)d_in[11];
    const float* bn2 = (const float*)d_in[12];
    const float* Wc1 = (const float*)d_in[13];
    const float* bc1 = (const float*)d_in[14];
    const float* Wc2 = (const float*)d_in[15];
    const float* gamma = (const float*)d_in[16];
    const float* beta  = (const float*)d_in[17];
    float* out = (float*)d_out;

    float *h, *hn, *x, *xn, *P, *Wsw, *bp, *aggS, *deg;
    cudaGetSymbolAddress((void**)&h,    g_h);
    cudaGetSymbolAddress((void**)&hn,   g_hn);
    cudaGetSymbolAddress((void**)&x,    g_x);
    cudaGetSymbolAddress((void**)&xn,   g_xn);
    cudaGetSymbolAddress((void**)&P,    g_P);
    cudaGetSymbolAddress((void**)&Wsw,  g_Wsw);
    cudaGetSymbolAddress((void**)&bp,   g_bp);
    cudaGetSymbolAddress((void**)&aggS, g_aggS);
    cudaGetSymbolAddress((void**)&deg,  g_deg);

    const int* srcI = eidx;
    const int* dstI = eidx + EE;

    prep_kernel<<<8, 256>>>(We2, be2, Wn1, bn1, Wc1, bc1, Wsw, bp);
    cudaMemcpyAsync(h, single, sizeof(float) * NN * CC, cudaMemcpyDeviceToDevice, 0);
    cudaMemcpyAsync(x, coords, sizeof(float) * NN * 3, cudaMemcpyDeviceToDevice, 0);
    cudaMemsetAsync(aggS, 0, sizeof(float) * (size_t)NN * 256, 0);
    cudaMemsetAsync(deg, 0, sizeof(float) * NN, 0);
    deg_kernel<<<(EE + 255) / 256, 256>>>(dstI, deg);

    for (int l = 0; l < 4; l++) {
        dim3 gp((NN + 127) / 128, 16);
        proj_kernel<<<gp, 256>>>(h, Wn1 + (size_t)l * 320 * 256, Wc1 + (size_t)l * 320 * 256, P, NN);
        cudaMemcpyAsync(xn, x, sizeof(float) * NN * 3, cudaMemcpyDeviceToDevice, 0);
        edge_kernel<<<EE / 64, 256>>>(
            srcI, dstI, dist,
            We1 + l * 64, be1 + l * 64,
            Wsw + (size_t)(2 * l) * 16384, bp + (2 * l) * 256,
            Wsw + (size_t)(2 * l + 1) * 16384, bp + (2 * l + 1) * 256,
            Wc2 + (size_t)l * 256,
            P, x, aggS, xn);
        dim3 gn((NN + 127) / 128, 2);
        nupd_kernel<<<gn, 256>>>(aggS, Wn2 + (size_t)l * 256 * 128, bn2 + l * 128, h, deg, hn, NN);
        if (l < 3) cudaMemsetAsync(aggS, 0, sizeof(float) * (size_t)NN * 256, 0);
        float* t;
        t = h; h = hn; hn = t;
        t = x; x = xn; xn = t;
    }
    ln_kernel<<<(NN * 32 + 255) / 256, 256>>>(h, x, gamma, beta, out);
}

// round 4
// speedup vs baseline: 2.1598x; 1.4854x over previous
#include <cuda_runtime.h>

#define NN 50000
#define EE 400000
#define CC 128

__device__ float g_h   [NN * CC];
__device__ float g_hn  [NN * CC];
__device__ float g_x   [NN * 3];
__device__ float g_xn  [NN * 3];
__device__ float g_P   [(size_t)NN * 1024];
__device__ float g_Wsw [8 * 64 * 256];
__device__ float g_bp  [8 * 256];
__device__ float g_aggS[(size_t)NN * 256];
__device__ int   g_cnt [NN];
__device__ int   g_off [NN];
__device__ int   g_srcS[EE];
__device__ int   g_dstS[EE];
__device__ float g_distS[EE];

__device__ __forceinline__ float siluf(float v) { return v / (1.f + __expf(-v)); }

__device__ __forceinline__ unsigned tf32r(float v) {
    unsigned u;
    asm("cvt.rna.tf32.f32 %0, %1;" : "=r"(u) : "f"(v));
    return u;
}

__device__ __forceinline__ void mma8(float* C, unsigned a0, unsigned a1, unsigned a2, unsigned a3,
                                     unsigned b0, unsigned b1) {
    asm volatile("mma.sync.aligned.m16n8k8.row.col.f32.tf32.tf32.f32 "
                 "{%0,%1,%2,%3}, {%4,%5,%6,%7}, {%8,%9}, {%0,%1,%2,%3};"
                 : "+f"(C[0]), "+f"(C[1]), "+f"(C[2]), "+f"(C[3])
                 : "r"(a0), "r"(a1), "r"(a2), "r"(a3), "r"(b0), "r"(b1));
}

__device__ __forceinline__ void redv2(float* addr, float v0, float v1) {
    asm volatile("red.global.add.v2.f32 [%0], {%1,%2};" :: "l"(addr), "f"(v0), "f"(v1) : "memory");
}

// ---------- sort by dst ----------
__global__ void hist_kernel(const int* __restrict__ dstIdx, int* __restrict__ cnt) {
    int e = blockIdx.x * blockDim.x + threadIdx.x;
    if (e < EE) atomicAdd(&cnt[dstIdx[e]], 1);
}

__global__ void scan_kernel(const int* __restrict__ cnt, int* __restrict__ off) {
    __shared__ int sa[1024], sb[1024];
    int t = threadIdx.x;
    int base = t * 49;
    int s = 0;
    for (int i = 0; i < 49; i++) { int r = base + i; if (r < NN) s += cnt[r]; }
    sa[t] = s;
    __syncthreads();
    int* in = sa; int* out = sb;
    for (int d = 1; d < 1024; d <<= 1) {
        out[t] = (t >= d) ? in[t] + in[t - d] : in[t];
        __syncthreads();
        int* tmp = in; in = out; out = tmp;
    }
    int run = (t > 0) ? in[t - 1] : 0;
    for (int i = 0; i < 49; i++) {
        int r = base + i;
        if (r < NN) { off[r] = run; run += cnt[r]; }
    }
}

__global__ void scatter_kernel(const int* __restrict__ srcIdx, const int* __restrict__ dstIdx,
                               const float* __restrict__ dist, int* __restrict__ off,
                               int* __restrict__ srcS, int* __restrict__ dstS,
                               float* __restrict__ distS) {
    int e = blockIdx.x * blockDim.x + threadIdx.x;
    if (e < EE) {
        int d = dstIdx[e];
        int pos = atomicAdd(&off[d], 1);
        srcS[pos] = srcIdx[e];
        dstS[pos] = d;
        distS[pos] = dist[e];
    }
}

// ---------- prep: fold We2/be2 into W1 rows [256:320), tf32 B-swizzled ----------
__global__ void prep_kernel(const float* __restrict__ We2, const float* __restrict__ be2,
                            const float* __restrict__ Wn1, const float* __restrict__ bn1,
                            const float* __restrict__ Wc1, const float* __restrict__ bc1,
                            float* __restrict__ Wsw, float* __restrict__ bp)
{
    int b = blockIdx.x, l = b >> 1, path = b & 1;
    const float* W1 = (path ? Wc1 : Wn1) + (size_t)l * 320 * 256;
    const float* bb = (path ? bc1 : bn1) + l * 256;
    const float* W2 = We2 + l * 64 * 64;
    const float* b2 = be2 + l * 64;
    int c = threadIdx.x;
    float acc[64];
#pragma unroll
    for (int k = 0; k < 64; k++) acc[k] = 0.f;
    float bacc = bb[c];
    for (int q = 0; q < 64; q++) {
        float w = W1[(size_t)(256 + q) * 256 + c];
        bacc += b2[q] * w;
#pragma unroll
        for (int k = 0; k < 64; k++) acc[k] += W2[k * 64 + q] * w;
    }
#pragma unroll
    for (int k = 0; k < 64; k++) {
        int idx = ((k >> 3) * 32 + (c >> 3)) * 64 + (c & 7) * 8 + (k & 3) * 2 + ((k & 7) >> 2);
        Wsw[(size_t)b * 16384 + idx] = __uint_as_float(tf32r(acc[k]));
    }
    bp[b * 256 + c] = bacc;
}

// ---------- P projections ----------
__global__ void __launch_bounds__(256) proj_kernel(const float* __restrict__ A,
                                                   const float* __restrict__ Wn1l,
                                                   const float* __restrict__ Wc1l,
                                                   float* __restrict__ P, int M)
{
    __shared__ float As[16][128];
    __shared__ float Bs[16][64];
    int bx = blockIdx.x, by = blockIdx.y;
    int q = by >> 2, colb = (by & 3) * 64;
    const float* W = (q < 2 ? Wn1l : Wc1l);
    int rowoff = (q & 1) * 128;
    int tid = threadIdx.x, tx = tid & 15, ty = tid >> 4;

    float acc[8][4];
#pragma unroll
    for (int i = 0; i < 8; i++)
#pragma unroll
        for (int j = 0; j < 4; j++) acc[i][j] = 0.f;

    for (int k0 = 0; k0 < 128; k0 += 16) {
#pragma unroll
        for (int s = 0; s < 2; s++) {
            int fid = tid * 2 + s;
            int r = fid >> 2, c4 = (fid & 3) << 2;
            int row = bx * 128 + r;
            float4 v = make_float4(0.f, 0.f, 0.f, 0.f);
            if (row < M) v = *(const float4*)(A + (size_t)row * 128 + k0 + c4);
            As[c4 + 0][r] = v.x; As[c4 + 1][r] = v.y; As[c4 + 2][r] = v.z; As[c4 + 3][r] = v.w;
        }
        {
            int r = tid >> 4, c4 = (tid & 15) << 2;
            *(float4*)(&Bs[r][c4]) = *(const float4*)(W + (size_t)(rowoff + k0 + r) * 256 + colb + c4);
        }
        __syncthreads();
#pragma unroll
        for (int k = 0; k < 16; k++) {
            float a[8];
#pragma unroll
            for (int i = 0; i < 8; i++) a[i] = As[k][ty * 8 + i];
            float4 b = *(const float4*)(&Bs[k][tx * 4]);
#pragma unroll
            for (int i = 0; i < 8; i++) {
                acc[i][0] += a[i] * b.x; acc[i][1] += a[i] * b.y;
                acc[i][2] += a[i] * b.z; acc[i][3] += a[i] * b.w;
            }
        }
        __syncthreads();
    }
#pragma unroll
    for (int i = 0; i < 8; i++) {
        int row = bx * 128 + ty * 8 + i;
        if (row < M)
            *(float4*)(P + (size_t)row * 1024 + by * 64 + tx * 4) =
                make_float4(acc[i][0], acc[i][1], acc[i][2], acc[i][3]);
    }
}

// ---------- path n edge kernel: 32 edges/block, 8 warps, tiles 16x64 ----------
__global__ void __launch_bounds__(256, 4) edgen_kernel(
    const int* __restrict__ srcS, const int* __restrict__ dstS,
    const float* __restrict__ distS,
    const float* __restrict__ We1l, const float* __restrict__ be1l,
    const float* __restrict__ Wswn, const float* __restrict__ bpn,
    const float* __restrict__ P, float* __restrict__ aggS)
{
    __shared__ float Ea[32 * 68];
    __shared__ float bpS[256];
    __shared__ int sIdx[32], dIdx[32];

    int tid = threadIdx.x;
    int lane = tid & 31, w = tid >> 5;
    int mt = w & 1, nt = w >> 1;
    int gid = lane >> 2, tig = lane & 3;
    int e0 = blockIdx.x * 32;

    if (tid < 32) { sIdx[tid] = srcS[e0 + tid]; dIdx[tid] = dstS[e0 + tid]; }
    bpS[tid] = bpn[tid];
    {
        int m = tid >> 3, seg = tid & 7;
        float d = distS[e0 + m];
#pragma unroll
        for (int kk = 0; kk < 8; kk++) {
            int k = seg * 8 + kk;
            Ea[m * 68 + k] = __uint_as_float(tf32r(siluf(fmaf(d, We1l[k], be1l[k]))));
        }
    }
    __syncthreads();

    int r0 = mt * 16 + gid, r1 = r0 + 8;
    int s0 = sIdx[r0], d0 = dIdx[r0];
    int s1 = sIdx[r1], d1 = dIdx[r1];

    float C[32];
#pragma unroll
    for (int i = 0; i < 32; i++) C[i] = 0.f;
#pragma unroll
    for (int kk = 0; kk < 8; kk++) {
        unsigned a0 = __float_as_uint(Ea[r0 * 68 + kk * 8 + tig]);
        unsigned a1 = __float_as_uint(Ea[r1 * 68 + kk * 8 + tig]);
        unsigned a2 = __float_as_uint(Ea[r0 * 68 + kk * 8 + tig + 4]);
        unsigned a3 = __float_as_uint(Ea[r1 * 68 + kk * 8 + tig + 4]);
#pragma unroll
        for (int j = 0; j < 8; j++) {
            float2 bb = *(const float2*)(Wswn + (size_t)(kk * 32 + nt * 8 + j) * 64 + lane * 2);
            mma8(C + j * 4, a0, a1, a2, a3, __float_as_uint(bb.x), __float_as_uint(bb.y));
        }
    }
#pragma unroll
    for (int j = 0; j < 8; j++) {
        int cc = (nt * 8 + j) * 8 + tig * 2;
        float2 bb = *(const float2*)(bpS + cc);
        float2 ps = *(const float2*)(P + (size_t)s0 * 1024 + cc);
        float2 pd = *(const float2*)(P + (size_t)d0 * 1024 + 256 + cc);
        float v0 = siluf(C[j * 4 + 0] + bb.x + ps.x + pd.x);
        float v1 = siluf(C[j * 4 + 1] + bb.y + ps.y + pd.y);
        redv2(aggS + (size_t)d0 * 256 + cc, v0, v1);
        ps = *(const float2*)(P + (size_t)s1 * 1024 + cc);
        pd = *(const float2*)(P + (size_t)d1 * 1024 + 256 + cc);
        v0 = siluf(C[j * 4 + 2] + bb.x + ps.x + pd.x);
        v1 = siluf(C[j * 4 + 3] + bb.y + ps.y + pd.y);
        redv2(aggS + (size_t)d1 * 256 + cc, v0, v1);
    }
}

// ---------- path c edge kernel ----------
__global__ void __launch_bounds__(256, 4) edgec_kernel(
    const int* __restrict__ srcS, const int* __restrict__ dstS,
    const float* __restrict__ distS,
    const float* __restrict__ We1l, const float* __restrict__ be1l,
    const float* __restrict__ Wswc, const float* __restrict__ bpc,
    const float* __restrict__ Wc2l,
    const float* __restrict__ P, const float* __restrict__ x,
    float* __restrict__ xn)
{
    __shared__ float Ea[32 * 68];
    __shared__ float bpS[256];
    __shared__ float Wc2s[256];
    __shared__ float cwP[128];
    __shared__ int sIdx[32], dIdx[32];

    int tid = threadIdx.x;
    int lane = tid & 31, w = tid >> 5;
    int mt = w & 1, nt = w >> 1;
    int gid = lane >> 2, tig = lane & 3;
    int e0 = blockIdx.x * 32;

    if (tid < 32) { sIdx[tid] = srcS[e0 + tid]; dIdx[tid] = dstS[e0 + tid]; }
    bpS[tid] = bpc[tid];
    Wc2s[tid] = Wc2l[tid];
    {
        int m = tid >> 3, seg = tid & 7;
        float d = distS[e0 + m];
#pragma unroll
        for (int kk = 0; kk < 8; kk++) {
            int k = seg * 8 + kk;
            Ea[m * 68 + k] = __uint_as_float(tf32r(siluf(fmaf(d, We1l[k], be1l[k]))));
        }
    }
    __syncthreads();

    int r0 = mt * 16 + gid, r1 = r0 + 8;
    int s0 = sIdx[r0], d0 = dIdx[r0];
    int s1 = sIdx[r1], d1 = dIdx[r1];

    float C[32];
#pragma unroll
    for (int i = 0; i < 32; i++) C[i] = 0.f;
#pragma unroll
    for (int kk = 0; kk < 8; kk++) {
        unsigned a0 = __float_as_uint(Ea[r0 * 68 + kk * 8 + tig]);
        unsigned a1 = __float_as_uint(Ea[r1 * 68 + kk * 8 + tig]);
        unsigned a2 = __float_as_uint(Ea[r0 * 68 + kk * 8 + tig + 4]);
        unsigned a3 = __float_as_uint(Ea[r1 * 68 + kk * 8 + tig + 4]);
#pragma unroll
        for (int j = 0; j < 8; j++) {
            float2 bb = *(const float2*)(Wswc + (size_t)(kk * 32 + nt * 8 + j) * 64 + lane * 2);
            mma8(C + j * 4, a0, a1, a2, a3, __float_as_uint(bb.x), __float_as_uint(bb.y));
        }
    }
    float p0 = 0.f, p1 = 0.f;
#pragma unroll
    for (int j = 0; j < 8; j++) {
        int cc = (nt * 8 + j) * 8 + tig * 2;
        float2 bb = *(const float2*)(bpS + cc);
        float2 wc = *(const float2*)(Wc2s + cc);
        float2 ps = *(const float2*)(P + (size_t)s0 * 1024 + 512 + cc);
        float2 pd = *(const float2*)(P + (size_t)d0 * 1024 + 768 + cc);
        p0 += siluf(C[j * 4 + 0] + bb.x + ps.x + pd.x) * wc.x
            + siluf(C[j * 4 + 1] + bb.y + ps.y + pd.y) * wc.y;
        ps = *(const float2*)(P + (size_t)s1 * 1024 + 512 + cc);
        pd = *(const float2*)(P + (size_t)d1 * 1024 + 768 + cc);
        p1 += siluf(C[j * 4 + 2] + bb.x + ps.x + pd.x) * wc.x
            + siluf(C[j * 4 + 3] + bb.y + ps.y + pd.y) * wc.y;
    }
    p0 += __shfl_xor_sync(0xffffffffu, p0, 1);
    p0 += __shfl_xor_sync(0xffffffffu, p0, 2);
    p1 += __shfl_xor_sync(0xffffffffu, p1, 1);
    p1 += __shfl_xor_sync(0xffffffffu, p1, 2);
    if (tig == 0) {
        cwP[r0 * 4 + nt] = p0;
        cwP[r1 * 4 + nt] = p1;
    }
    __syncthreads();
    if (tid < 32) {
        float cw = cwP[tid * 4] + cwP[tid * 4 + 1] + cwP[tid * 4 + 2] + cwP[tid * 4 + 3];
        int s = sIdx[tid], dd = dIdx[tid];
        float u0 = cw * (x[(size_t)s * 3 + 0] - x[(size_t)dd * 3 + 0]);
        float u1 = cw * (x[(size_t)s * 3 + 1] - x[(size_t)dd * 3 + 1]);
        float u2 = cw * (x[(size_t)s * 3 + 2] - x[(size_t)dd * 3 + 2]);
        atomicAdd(&xn[(size_t)dd * 3 + 0], u0);
        atomicAdd(&xn[(size_t)dd * 3 + 1], u1);
        atomicAdd(&xn[(size_t)dd * 3 + 2], u2);
    }
}

// ---------- hn = h + aggS @ Wn2 + deg * bn2 ----------
__global__ void __launch_bounds__(256) nupd_kernel(const float* __restrict__ A,
                                                   const float* __restrict__ W,
                                                   const float* __restrict__ bn2l,
                                                   const float* __restrict__ hprev,
                                                   const int* __restrict__ deg,
                                                   float* __restrict__ hn, int M)
{
    __shared__ float As[16][128];
    __shared__ float Bs[16][64];
    int bx = blockIdx.x, by = blockIdx.y;
    int colb = by * 64;
    int tid = threadIdx.x, tx = tid & 15, ty = tid >> 4;

    float acc[8][4];
#pragma unroll
    for (int i = 0; i < 8; i++)
#pragma unroll
        for (int j = 0; j < 4; j++) acc[i][j] = 0.f;

    for (int k0 = 0; k0 < 256; k0 += 16) {
#pragma unroll
        for (int s = 0; s < 2; s++) {
            int fid = tid * 2 + s;
            int r = fid >> 2, c4 = (fid & 3) << 2;
            int row = bx * 128 + r;
            float4 v = make_float4(0.f, 0.f, 0.f, 0.f);
            if (row < M) v = *(const float4*)(A + (size_t)row * 256 + k0 + c4);
            As[c4 + 0][r] = v.x; As[c4 + 1][r] = v.y; As[c4 + 2][r] = v.z; As[c4 + 3][r] = v.w;
        }
        {
            int r = tid >> 4, c4 = (tid & 15) << 2;
            *(float4*)(&Bs[r][c4]) = *(const float4*)(W + (size_t)(k0 + r) * 128 + colb + c4);
        }
        __syncthreads();
#pragma unroll
        for (int k = 0; k < 16; k++) {
            float a[8];
#pragma unroll
            for (int i = 0; i < 8; i++) a[i] = As[k][ty * 8 + i];
            float4 b = *(const float4*)(&Bs[k][tx * 4]);
#pragma unroll
            for (int i = 0; i < 8; i++) {
                acc[i][0] += a[i] * b.x; acc[i][1] += a[i] * b.y;
                acc[i][2] += a[i] * b.z; acc[i][3] += a[i] * b.w;
            }
        }
        __syncthreads();
    }
#pragma unroll
    for (int i = 0; i < 8; i++) {
        int row = bx * 128 + ty * 8 + i;
        if (row < M) {
            int col = colb + tx * 4;
            float dg = (float)deg[row];
            float4 hh = *(const float4*)(hprev + (size_t)row * 128 + col);
            float4 bb = *(const float4*)(bn2l + col);
            float4 o;
            o.x = acc[i][0] + hh.x + dg * bb.x;
            o.y = acc[i][1] + hh.y + dg * bb.y;
            o.z = acc[i][2] + hh.z + dg * bb.z;
            o.w = acc[i][3] + hh.w + dg * bb.w;
            *(float4*)(hn + (size_t)row * 128 + col) = o;
        }
    }
}

__global__ void ln_kernel(const float* __restrict__ h, const float* __restrict__ x,
                          const float* __restrict__ gamma, const float* __restrict__ beta,
                          float* __restrict__ out)
{
    int g = blockIdx.x * blockDim.x + threadIdx.x;
    int w = g >> 5, lane = g & 31;
    if (w < NN) {
        const float* row = h + (size_t)w * CC;
        float v0 = row[lane], v1 = row[lane + 32], v2 = row[lane + 64], v3 = row[lane + 96];
        float s = v0 + v1 + v2 + v3;
#pragma unroll
        for (int o = 16; o > 0; o >>= 1) s += __shfl_xor_sync(0xffffffffu, s, o);
        float mu = s * (1.f / 128.f);
        float d0 = v0 - mu, d1 = v1 - mu, d2 = v2 - mu, d3 = v3 - mu;
        float q = d0 * d0 + d1 * d1 + d2 * d2 + d3 * d3;
#pragma unroll
        for (int o = 16; o > 0; o >>= 1) q += __shfl_xor_sync(0xffffffffu, q, o);
        float rs = rsqrtf(q * (1.f / 128.f) + 1e-5f);
        float* orow = out + (size_t)w * CC;
        orow[lane]      = gamma[lane]      * d0 * rs + beta[lane];
        orow[lane + 32] = gamma[lane + 32] * d1 * rs + beta[lane + 32];
        orow[lane + 64] = gamma[lane + 64] * d2 * rs + beta[lane + 64];
        orow[lane + 96] = gamma[lane + 96] * d3 * rs + beta[lane + 96];
    }
    int stride = gridDim.x * blockDim.x;
    for (int j = g; j < NN * 3; j += stride) out[(size_t)NN * CC + j] = x[j];
}

extern "C" void kernel_launch(void* const* d_in, const int* in_sizes, int n_in,
                              void* d_out, int out_size)
{
    (void)in_sizes; (void)n_in; (void)out_size;
    const float* single = (const float*)d_in[0];
    const float* coords = (const float*)d_in[2];
    const int*   eidx   = (const int*)d_in[3];
    const float* dist   = (const float*)d_in[4];
    const float* We1 = (const float*)d_in[5];
    const float* be1 = (const float*)d_in[6];
    const float* We2 = (const float*)d_in[7];
    const float* be2 = (const float*)d_in[8];
    const float* Wn1 = (const float*)d_in[9];
    const float* bn1 = (const float*)d_in[10];
    const float* Wn2 = (const float*)d_in[11];
    const float* bn2 = (const float*)d_in[12];
    const float* Wc1 = (const float*)d_in[13];
    const float* bc1 = (const float*)d_in[14];
    const float* Wc2 = (const float*)d_in[15];
    const float* gamma = (const float*)d_in[16];
    const float* beta  = (const float*)d_in[17];
    float* out = (float*)d_out;

    float *h, *hn, *x, *xn, *P, *Wsw, *bp, *aggS, *distS;
    int *cnt, *off, *srcS, *dstS;
    cudaGetSymbolAddress((void**)&h,    g_h);
    cudaGetSymbolAddress((void**)&hn,   g_hn);
    cudaGetSymbolAddress((void**)&x,    g_x);
    cudaGetSymbolAddress((void**)&xn,   g_xn);
    cudaGetSymbolAddress((void**)&P,    g_P);
    cudaGetSymbolAddress((void**)&Wsw,  g_Wsw);
    cudaGetSymbolAddress((void**)&bp,   g_bp);
    cudaGetSymbolAddress((void**)&aggS, g_aggS);
    cudaGetSymbolAddress((void**)&cnt,  g_cnt);
    cudaGetSymbolAddress((void**)&off,  g_off);
    cudaGetSymbolAddress((void**)&srcS, g_srcS);
    cudaGetSymbolAddress((void**)&dstS, g_dstS);
    cudaGetSymbolAddress((void**)&distS,g_distS);

    const int* srcI = eidx;
    const int* dstI = eidx + EE;

    prep_kernel<<<8, 256>>>(We2, be2, Wn1, bn1, Wc1, bc1, Wsw, bp);
    cudaMemcpyAsync(h, single, sizeof(float) * NN * CC, cudaMemcpyDeviceToDevice, 0);
    cudaMemcpyAsync(x, coords, sizeof(float) * NN * 3, cudaMemcpyDeviceToDevice, 0);
    cudaMemsetAsync(aggS, 0, sizeof(float) * (size_t)NN * 256, 0);
    cudaMemsetAsync(cnt, 0, sizeof(int) * NN, 0);
    hist_kernel<<<(EE + 255) / 256, 256>>>(dstI, cnt);
    scan_kernel<<<1, 1024>>>(cnt, off);
    scatter_kernel<<<(EE + 255) / 256, 256>>>(srcI, dstI, dist, off, srcS, dstS, distS);

    for (int l = 0; l < 4; l++) {
        dim3 gp((NN + 127) / 128, 16);
        proj_kernel<<<gp, 256>>>(h, Wn1 + (size_t)l * 320 * 256, Wc1 + (size_t)l * 320 * 256, P, NN);
        cudaMemcpyAsync(xn, x, sizeof(float) * NN * 3, cudaMemcpyDeviceToDevice, 0);
        edgen_kernel<<<EE / 32, 256>>>(srcS, dstS, distS,
            We1 + l * 64, be1 + l * 64,
            Wsw + (size_t)(2 * l) * 16384, bp + (2 * l) * 256,
            P, aggS);
        edgec_kernel<<<EE / 32, 256>>>(srcS, dstS, distS,
            We1 + l * 64, be1 + l * 64,
            Wsw + (size_t)(2 * l + 1) * 16384, bp + (2 * l + 1) * 256,
            Wc2 + (size_t)l * 256,
            P, x, xn);
        dim3 gn((NN + 127) / 128, 2);
        nupd_kernel<<<gn, 256>>>(aggS, Wn2 + (size_t)l * 256 * 128, bn2 + l * 128, h, cnt, hn, NN);
        if (l < 3) cudaMemsetAsync(aggS, 0, sizeof(float) * (size_t)NN * 256, 0);
        float* t;
        t = h; h = hn; hn = t;
        t = x; x = xn; xn = t;
    }
    ln_kernel<<<(NN * 32 + 255) / 256, 256>>>(h, x, gamma, beta, out);
}